// round 6
// baseline (speedup 1.0000x reference)
#include <cuda_runtime.h>
#include <cuda_bf16.h>
#include <cstdint>
#include <cstddef>

#define Bq   2
#define Cq   512
#define CKq  64
#define Nq   4096

// ---------------- scratch (device globals: allocation-free) ----------------
__device__ float g_fx[(size_t)Bq * CKq * Nq];        // 2 MB
__device__ float g_gx[(size_t)Bq * CKq * Nq];        // 2 MB
__device__ float g_hx[(size_t)Bq * Cq * Nq];         // 16 MB (only if gamma != 0)
__device__ int   g_fmax2i;                           // max_i ||f_col_i||^2 (float bits)
__device__ int   g_gmax2i;                           // max_j ||g_col_j||^2 (float bits)

// packed dual-FMA (sm_103a FFMA2) — 2x fp32 FMA throughput
__device__ __forceinline__ float2 ffma2(float2 a, float2 b, float2 c) {
    float2 d;
    asm("fma.rn.f32x2 %0, %1, %2, %3;"
        : "=l"(reinterpret_cast<unsigned long long&>(d))
        : "l"(reinterpret_cast<unsigned long long&>(a)),
          "l"(reinterpret_cast<unsigned long long&>(b)),
          "l"(reinterpret_cast<unsigned long long&>(c)));
    return d;
}

__device__ __forceinline__ void cp_async16(uint32_t saddr, const void* gptr) {
    asm volatile("cp.async.cg.shared.global [%0], [%1], 16;" :: "r"(saddr), "l"(gptr));
}
__device__ __forceinline__ void cp_commit() {
    asm volatile("cp.async.commit_group;");
}
__device__ __forceinline__ void cp_wait_all() {
    asm volatile("cp.async.wait_group 0;");
}

// ---------------------------------------------------------------------------
__global__ void init_kernel() {
    if (threadIdx.x == 0) { g_fmax2i = 0; g_gmax2i = 0; }
}

// ---------------------------------------------------------------------------
// Kernel P: projections. grid = (32 n-tiles, 10 row-groups, B)
//   y==0 -> fx, y==1 -> gx (both also reduce per-column norm^2 into atomics),
//   y in [2,10) -> hx rows (skipped when gamma==0)
// ---------------------------------------------------------------------------
__global__ void proj_kernel(const float* __restrict__ x,
                            const float* __restrict__ f_w, const float* __restrict__ f_b,
                            const float* __restrict__ g_w, const float* __restrict__ g_b,
                            const float* __restrict__ h_w, const float* __restrict__ h_b,
                            const float* __restrict__ gamma)
{
    const int nt = blockIdx.x;
    const int yb = blockIdx.y;
    const int b  = blockIdx.z;

    const float* w; const float* bias; float* dst;
    if (yb == 0)      { w = f_w; bias = f_b; dst = g_fx + (size_t)b * CKq * Nq; }
    else if (yb == 1) { w = g_w; bias = g_b; dst = g_gx + (size_t)b * CKq * Nq; }
    else {
        if (gamma[0] == 0.0f) return;
        const int rb = (yb - 2) * 64;
        w    = h_w + (size_t)rb * Cq;
        bias = h_b + rb;
        dst  = g_hx + (size_t)b * Cq * Nq + (size_t)rb * Nq;
    }

    __shared__ float ws[64][32];
    __shared__ float xs[32][128];
    __shared__ float colsq[128];

    const int tid  = threadIdx.x;          // 256
    const int kg   = tid >> 5;
    const int nsub = tid & 31;
    const int n0   = nt * 128;
    const float* xb = x + (size_t)b * Cq * Nq;

    float acc[8][4];
#pragma unroll
    for (int a = 0; a < 8; a++)
#pragma unroll
        for (int q = 0; q < 4; q++) acc[a][q] = 0.f;

    for (int c0 = 0; c0 < Cq; c0 += 32) {
        for (int i = tid; i < 64 * 32; i += 256) {
            int k = i >> 5, c = i & 31;
            ws[k][c] = w[(size_t)k * Cq + c0 + c];
        }
        for (int i = tid; i < 32 * 128; i += 256) {
            int c = i >> 7, n = i & 127;
            xs[c][n] = xb[(size_t)(c0 + c) * Nq + n0 + n];
        }
        __syncthreads();
#pragma unroll
        for (int c = 0; c < 32; c++) {
            float4 xv = *(const float4*)&xs[c][nsub * 4];
#pragma unroll
            for (int kk = 0; kk < 8; kk++) {
                float wv = ws[kg * 8 + kk][c];
                acc[kk][0] += wv * xv.x;
                acc[kk][1] += wv * xv.y;
                acc[kk][2] += wv * xv.z;
                acc[kk][3] += wv * xv.w;
            }
        }
        __syncthreads();
    }

    if (yb < 2 && tid < 128) colsq[tid] = 0.f;
    if (yb < 2) __syncthreads();

    float sq[4] = {0.f, 0.f, 0.f, 0.f};
#pragma unroll
    for (int kk = 0; kk < 8; kk++) {
        int k = kg * 8 + kk;
        float bb = bias[k];
        float v0 = acc[kk][0] + bb, v1 = acc[kk][1] + bb;
        float v2 = acc[kk][2] + bb, v3 = acc[kk][3] + bb;
        *(float4*)&dst[(size_t)k * Nq + n0 + nsub * 4] = make_float4(v0, v1, v2, v3);
        sq[0] += v0 * v0; sq[1] += v1 * v1; sq[2] += v2 * v2; sq[3] += v3 * v3;
    }

    if (yb < 2) {
#pragma unroll
        for (int q = 0; q < 4; q++) atomicAdd(&colsq[nsub * 4 + q], sq[q]);
        __syncthreads();
        if (tid < 128) {
            int* tgt = (yb == 0) ? &g_fmax2i : &g_gmax2i;
            atomicMax(tgt, __float_as_int(colsq[tid]));
        }
    }
}

// ---------------------------------------------------------------------------
// Fused energy + softmax kernel.
// grid = (128 i-tiles of 32 rows, B), block = 128 threads, 1 CTA/SM (big smem).
// Per block: fs[64][32] resident, gx streamed in (32k x 512j) cp.async-double-
// buffered stages. Thread tile 8i x 16j (FFMA2). After each 512-j chunk:
// p = exp(e - m) written unnormalized to attn, row sums accumulated in regs.
// Epilogue: warp-reduce row sums, rescale the block's 32 rows in place (L2-hot).
// ---------------------------------------------------------------------------
__global__ __launch_bounds__(128, 1) void fused_kernel(float* __restrict__ attn)
{
    extern __shared__ float sh[];
    float* fs   = sh;                      // [64][32]
    float* gsb0 = sh + 64 * 32;            // [32][512]
    float* gsb1 = gsb0 + 32 * 512;         // [32][512]
    float* srow = gsb1 + 32 * 512;         // [32]

    const int it = blockIdx.x, b = blockIdx.y;
    const int i0 = it * 32;
    const int tid = threadIdx.x;           // 128
    const int ig  = tid >> 5;              // 0..3  (warp id; 8 rows each)
    const int jg  = tid & 31;              // lane

    const float* fxp = g_fx + (size_t)b * CKq * Nq;
    const float* gxp = g_gx + (size_t)b * CKq * Nq;
    float* ap = attn + (size_t)b * Nq * Nq;

    const float m = sqrtf(__int_as_float(g_fmax2i)) * sqrtf(__int_as_float(g_gmax2i));

    // load fs: fx rows [0,64) cols [i0, i0+32)
    for (int idx = tid; idx < 64 * 32; idx += 128) {
        int r = idx >> 5, c = idx & 31;
        fs[idx] = fxp[(size_t)r * Nq + i0 + c];
    }

    // prologue: stage 0 (jc=0, kh=0) -> gsb0
    {
        uint32_t sb = (uint32_t)__cvta_generic_to_shared(gsb0);
#pragma unroll
        for (int t = 0; t < 32; t++) {
            int idx = tid + t * 128;            // float4 index into [32][128]
            int r = idx >> 7, c4 = idx & 127;
            cp_async16(sb + (uint32_t)(r * 512 + c4 * 4) * 4,
                       gxp + (size_t)r * Nq + c4 * 4);
        }
        cp_commit();
    }
    __syncthreads();   // fs visible

    float2 acc[8][8];
#pragma unroll
    for (int ii = 0; ii < 8; ii++)
#pragma unroll
        for (int p = 0; p < 8; p++) acc[ii][p] = make_float2(0.f, 0.f);
    float rsum[8] = {0.f,0.f,0.f,0.f,0.f,0.f,0.f,0.f};

    for (int s = 0; s < 16; s++) {
        const int jc = s >> 1, kh = s & 1;
        const int j0 = jc * 512;

        cp_wait_all();
        __syncthreads();   // current buffer filled; everyone done with the other

        if (s + 1 < 16) {
            const int jn = (s + 1) >> 1, kn = (s + 1) & 1;
            float* nb = ((s + 1) & 1) ? gsb1 : gsb0;
            uint32_t sb = (uint32_t)__cvta_generic_to_shared(nb);
            const float* src = gxp + (size_t)(kn * 32) * Nq + jn * 512;
#pragma unroll
            for (int t = 0; t < 32; t++) {
                int idx = tid + t * 128;
                int r = idx >> 7, c4 = idx & 127;
                cp_async16(sb + (uint32_t)(r * 512 + c4 * 4) * 4,
                           src + (size_t)r * Nq + c4 * 4);
            }
            cp_commit();
        }

        const float* gb = (s & 1) ? gsb1 : gsb0;
        const int kbase = kh * 32;
#pragma unroll 4
        for (int k = 0; k < 32; k++) {
            float fv[8];
#pragma unroll
            for (int ii = 0; ii < 8; ii++)
                fv[ii] = fs[(kbase + k) * 32 + ig * 8 + ii];
#pragma unroll
            for (int q = 0; q < 4; q++) {
                float4 g4 = *(const float4*)&gb[k * 512 + q * 128 + jg * 4];
                float2 glo = make_float2(g4.x, g4.y);
                float2 ghi = make_float2(g4.z, g4.w);
#pragma unroll
                for (int ii = 0; ii < 8; ii++) {
                    float2 fp = make_float2(fv[ii], fv[ii]);
                    acc[ii][q * 2]     = ffma2(fp, glo, acc[ii][q * 2]);
                    acc[ii][q * 2 + 1] = ffma2(fp, ghi, acc[ii][q * 2 + 1]);
                }
            }
        }

        if (kh == 1) {
            // chunk complete: exponentiate, write unnormalized, accumulate row sums
#pragma unroll
            for (int ii = 0; ii < 8; ii++) {
                float* row = ap + (size_t)(i0 + ig * 8 + ii) * Nq + j0;
#pragma unroll
                for (int q = 0; q < 4; q++) {
                    float e0 = __expf(acc[ii][q*2].x   - m);
                    float e1 = __expf(acc[ii][q*2].y   - m);
                    float e2 = __expf(acc[ii][q*2+1].x - m);
                    float e3 = __expf(acc[ii][q*2+1].y - m);
                    *(float4*)&row[q * 128 + jg * 4] = make_float4(e0, e1, e2, e3);
                    rsum[ii] += (e0 + e1) + (e2 + e3);
                    acc[ii][q*2]   = make_float2(0.f, 0.f);
                    acc[ii][q*2+1] = make_float2(0.f, 0.f);
                }
            }
        }
    }

    // reduce row sums across the warp (each warp owns 8 rows)
#pragma unroll
    for (int ii = 0; ii < 8; ii++) {
        float r = rsum[ii];
#pragma unroll
        for (int o = 16; o > 0; o >>= 1) r += __shfl_xor_sync(0xffffffffu, r, o);
        if (jg == 0) srow[ig * 8 + ii] = r;
    }
    __syncthreads();
    if (tid < 32) srow[tid] = 1.0f / srow[tid];
    __syncthreads();

    // scale pass: 32 rows x 4096, float4, mostly L2-resident
    for (int idx = tid; idx < 32 * 1024; idx += 128) {
        int row = idx >> 10;
        int c   = (idx & 1023) * 4;
        float inv = srow[row];
        float* p = ap + (size_t)(i0 + row) * Nq + c;
        float4 v = *(float4*)p;
        v.x *= inv; v.y *= inv; v.z *= inv; v.w *= inv;
        *(float4*)p = v;
    }
}

// ---------------------------------------------------------------------------
// Kernel O: out = gamma * (hx @ attn^T) + x. gamma==0 -> copy (live path).
// ---------------------------------------------------------------------------
__global__ void out_kernel(const float* __restrict__ x,
                           const float* __restrict__ gamma,
                           const float* __restrict__ attn,
                           float* __restrict__ out)
{
    const float g = gamma[0];
    const int it = blockIdx.x, ct = blockIdx.y, b = blockIdx.z;
    const int tid = threadIdx.x;

    if (g == 0.0f) {
        for (int e = tid; e < 64 * 32; e += 256) {
            int c = e >> 5, i4 = e & 31;
            size_t off = ((size_t)b * Cq + ct * 64 + c) * Nq + (size_t)it * 128 + i4 * 4;
            *(float4*)&out[off] = *(const float4*)&x[off];
        }
        return;
    }
    // general fallback (gamma != 0): correct but slow
    for (int e = tid; e < 64 * 128; e += 256) {
        int c = ct * 64 + (e >> 7);
        int i = it * 128 + (e & 127);
        const float* hp = g_hx + ((size_t)b * Cq + c) * Nq;
        const float* apr = attn + ((size_t)b * Nq + i) * Nq;
        float s = 0.f;
        for (int j = 0; j < Nq; j++) s += hp[j] * apr[j];
        size_t off = ((size_t)b * Cq + c) * Nq + i;
        out[off] = g * s + x[off];
    }
}

// ---------------------------------------------------------------------------
extern "C" void kernel_launch(void* const* d_in, const int* in_sizes, int n_in,
                              void* d_out, int out_size)
{
    (void)in_sizes; (void)n_in;
    const float* x    = (const float*)d_in[0];
    const float* f_w  = (const float*)d_in[1];
    const float* f_b  = (const float*)d_in[2];
    const float* g_w  = (const float*)d_in[3];
    const float* g_b  = (const float*)d_in[4];
    const float* h_w  = (const float*)d_in[5];
    const float* h_b  = (const float*)d_in[6];
    const float* gam  = (const float*)d_in[7];

    float* out  = (float*)d_out;
    float* attn = out + ((size_t)out_size - (size_t)Bq * Nq * Nq);

    static bool attr_set = false;
    if (!attr_set) {
        cudaFuncSetAttribute(fused_kernel,
                             cudaFuncAttributeMaxDynamicSharedMemorySize, 140 * 1024);
        attr_set = true;
    }

    const int fused_smem = (64 * 32 + 2 * 32 * 512 + 32) * 4;

    init_kernel<<<1, 32>>>();
    proj_kernel<<<dim3(32, 10, Bq), 256>>>(x, f_w, f_b, g_w, g_b, h_w, h_b, gam);
    fused_kernel<<<dim3(128, Bq), 128, fused_smem>>>(attn);
    out_kernel<<<dim3(32, 8, Bq), 256>>>(x, gam, attn, out);
}

// round 8
// speedup vs baseline: 2.3911x; 2.3911x over previous
#include <cuda_runtime.h>
#include <cuda_bf16.h>
#include <cstdint>
#include <cstddef>

#define Bq   2
#define Cq   512
#define CKq  64
#define Nq   4096

// ---------------- scratch (device globals: allocation-free) ----------------
__device__ __nv_bfloat16 g_fh[(size_t)Bq * Nq * CKq];   // fx hi, [n][k]
__device__ __nv_bfloat16 g_fl[(size_t)Bq * Nq * CKq];   // fx lo residual
__device__ __nv_bfloat16 g_gh[(size_t)Bq * Nq * CKq];   // gx hi
__device__ __nv_bfloat16 g_gl[(size_t)Bq * Nq * CKq];   // gx lo
__device__ float g_hx[(size_t)Bq * Cq * Nq];            // gamma != 0 only
__device__ float g_rowsum[(size_t)Bq * Nq];             // softmax denominators
__device__ int   g_fmax2i;                              // max_i ||f_col_i||^2 bits
__device__ int   g_gmax2i;                              // max_j ||g_col_j||^2 bits

// ------------------------------ PTX helpers -------------------------------
__device__ __forceinline__ uint32_t smem_u32(const void* p) {
    uint32_t a;
    asm("{ .reg .u64 t; cvta.to.shared.u64 t, %1; cvt.u32.u64 %0, t; }"
        : "=r"(a) : "l"(p));
    return a;
}
#define SWZ128(o) ((o) ^ (((o) >> 3) & 0x70))

__device__ __forceinline__ void cp16(uint32_t s, const void* g) {
    asm volatile("cp.async.cg.shared.global [%0], [%1], 16;" :: "r"(s), "l"(g));
}
__device__ __forceinline__ void cp_commit() { asm volatile("cp.async.commit_group;"); }
__device__ __forceinline__ void cp_wait0()  { asm volatile("cp.async.wait_group 0;"); }
__device__ __forceinline__ void cp_wait1()  { asm volatile("cp.async.wait_group 1;"); }

__device__ __forceinline__ void ldmx4(uint32_t* r, uint32_t addr) {
    asm volatile("ldmatrix.sync.aligned.m8n8.x4.shared.b16 {%0,%1,%2,%3}, [%4];"
        : "=r"(r[0]), "=r"(r[1]), "=r"(r[2]), "=r"(r[3]) : "r"(addr));
}
__device__ __forceinline__ void ldmx2(uint32_t* r, uint32_t addr) {
    asm volatile("ldmatrix.sync.aligned.m8n8.x2.shared.b16 {%0,%1}, [%2];"
        : "=r"(r[0]), "=r"(r[1]) : "r"(addr));
}
__device__ __forceinline__ void mma_bf16(float* c, const uint32_t* a, const uint32_t* b) {
    asm volatile("mma.sync.aligned.m16n8k16.row.col.f32.bf16.bf16.f32 "
        "{%0,%1,%2,%3}, {%4,%5,%6,%7}, {%8,%9}, {%0,%1,%2,%3};"
        : "+f"(c[0]), "+f"(c[1]), "+f"(c[2]), "+f"(c[3])
        : "r"(a[0]), "r"(a[1]), "r"(a[2]), "r"(a[3]), "r"(b[0]), "r"(b[1]));
}

// ---------------------------------------------------------------------------
__global__ void init_kernel() {
    int i = blockIdx.x * blockDim.x + threadIdx.x;
    if (i < Bq * Nq) g_rowsum[i] = 0.f;
    if (i == 0) { g_fmax2i = 0; g_gmax2i = 0; }
}

// ---------------------------------------------------------------------------
// Kernel P: projections. grid = (32 n-tiles, 10 row-groups, B)
//   yb==0 -> fx (bf16 hi/lo, [n][k]), yb==1 -> gx likewise; both reduce
//   per-column norm^2 into global atomicMax. yb>=2 -> hx fp32 (gamma!=0 only).
// ---------------------------------------------------------------------------
__global__ void proj_kernel(const float* __restrict__ x,
                            const float* __restrict__ f_w, const float* __restrict__ f_b,
                            const float* __restrict__ g_w, const float* __restrict__ g_b,
                            const float* __restrict__ h_w, const float* __restrict__ h_b,
                            const float* __restrict__ gamma)
{
    const int nt = blockIdx.x;
    const int yb = blockIdx.y;
    const int b  = blockIdx.z;

    const float* w; const float* bias;
    float* hx_dst = nullptr;
    __nv_bfloat16* hdst = nullptr; __nv_bfloat16* ldst = nullptr;
    if (yb == 0) {
        w = f_w; bias = f_b;
        hdst = g_fh + (size_t)b * Nq * CKq; ldst = g_fl + (size_t)b * Nq * CKq;
    } else if (yb == 1) {
        w = g_w; bias = g_b;
        hdst = g_gh + (size_t)b * Nq * CKq; ldst = g_gl + (size_t)b * Nq * CKq;
    } else {
        if (gamma[0] == 0.0f) return;
        const int rb = (yb - 2) * 64;
        w    = h_w + (size_t)rb * Cq;
        bias = h_b + rb;
        hx_dst = g_hx + (size_t)b * Cq * Nq + (size_t)rb * Nq;
    }

    __shared__ float ws[64][32];
    __shared__ float xs[32][128];
    __shared__ float colsq[128];

    const int tid  = threadIdx.x;          // 256
    const int kg   = tid >> 5;
    const int nsub = tid & 31;
    const int n0   = nt * 128;
    const float* xb = x + (size_t)b * Cq * Nq;

    float acc[8][4];
#pragma unroll
    for (int a = 0; a < 8; a++)
#pragma unroll
        for (int q = 0; q < 4; q++) acc[a][q] = 0.f;

    for (int c0 = 0; c0 < Cq; c0 += 32) {
        for (int i = tid; i < 64 * 32; i += 256) {
            int k = i >> 5, c = i & 31;
            ws[k][c] = w[(size_t)k * Cq + c0 + c];
        }
        for (int i = tid; i < 32 * 128; i += 256) {
            int c = i >> 7, n = i & 127;
            xs[c][n] = xb[(size_t)(c0 + c) * Nq + n0 + n];
        }
        __syncthreads();
#pragma unroll
        for (int c = 0; c < 32; c++) {
            float4 xv = *(const float4*)&xs[c][nsub * 4];
#pragma unroll
            for (int kk = 0; kk < 8; kk++) {
                float wv = ws[kg * 8 + kk][c];
                acc[kk][0] += wv * xv.x;
                acc[kk][1] += wv * xv.y;
                acc[kk][2] += wv * xv.z;
                acc[kk][3] += wv * xv.w;
            }
        }
        __syncthreads();
    }

    if (yb >= 2) {
#pragma unroll
        for (int kk = 0; kk < 8; kk++) {
            int k = kg * 8 + kk;
            float bb = bias[k];
            float4 o = make_float4(acc[kk][0] + bb, acc[kk][1] + bb,
                                   acc[kk][2] + bb, acc[kk][3] + bb);
            *(float4*)&hx_dst[(size_t)k * Nq + n0 + nsub * 4] = o;
        }
        return;
    }

    if (tid < 128) colsq[tid] = 0.f;
    __syncthreads();

    float bb[8];
#pragma unroll
    for (int kk = 0; kk < 8; kk++) bb[kk] = bias[kg * 8 + kk];

    float sq[4] = {0.f, 0.f, 0.f, 0.f};
#pragma unroll
    for (int q = 0; q < 4; q++) {
        __nv_bfloat16 h8[8] __align__(16);
        __nv_bfloat16 l8[8] __align__(16);
#pragma unroll
        for (int kk = 0; kk < 8; kk++) {
            float v = acc[kk][q] + bb[kk];
            __nv_bfloat16 hi = __float2bfloat16(v);
            float lo = v - __bfloat162float(hi);
            h8[kk] = hi;
            l8[kk] = __float2bfloat16(lo);
            sq[q] += v * v;
        }
        const int n = n0 + nsub * 4 + q;
        *(uint4*)&hdst[(size_t)n * CKq + kg * 8] = *(const uint4*)h8;
        *(uint4*)&ldst[(size_t)n * CKq + kg * 8] = *(const uint4*)l8;
    }

#pragma unroll
    for (int q = 0; q < 4; q++) atomicAdd(&colsq[nsub * 4 + q], sq[q]);
    __syncthreads();
    if (tid < 128) {
        int* tgt = (yb == 0) ? &g_fmax2i : &g_gmax2i;
        atomicMax(tgt, __float_as_int(colsq[tid]));
    }
}

// ---------------------------------------------------------------------------
// Energy+softmax kernel (warp-level bf16 MMA, hi/lo split, two launches):
//   pass 0: accumulate rowsums of exp(e - m) into g_rowsum (atomics)
//   pass 1: recompute identical energies, write exp(e - m)/rowsum to attn
// grid = (4 j-chunks of 1024, 32 i-tiles of 128, B), 256 threads (8 warps).
// Warp tile 64i x 32j; CTA tile 128 x 128 per inner chunk, 8 chunks.
// SMEM: A hi/lo resident (32KB) + B hi/lo double-buffered (64KB), swizzled.
// ---------------------------------------------------------------------------
__device__ __forceinline__ void load_b_chunk(const __nv_bfloat16* gh,
                                             const __nv_bfloat16* gl,
                                             int jrow0, uint32_t BH, uint32_t BL,
                                             int tid)
{
    const __nv_bfloat16* sh = gh + (size_t)jrow0 * CKq;
    const __nv_bfloat16* sl = gl + (size_t)jrow0 * CKq;
    for (int e = tid; e < 1024; e += 256) {
        int r = e >> 3, c = e & 7;
        uint32_t sw = SWZ128((uint32_t)(r * 128 + c * 16));
        cp16(BH + sw, sh + (size_t)r * CKq + c * 8);
        cp16(BL + sw, sl + (size_t)r * CKq + c * 8);
    }
}

__global__ __launch_bounds__(256) void energy_kernel(float* __restrict__ attn, int pass)
{
    extern __shared__ char smraw[];
    const uint32_t sm0  = smem_u32(smraw);
    const uint32_t base = (sm0 + 1023u) & ~1023u;
    char* bp = smraw + (base - sm0);

    const uint32_t A_H = base;
    const uint32_t A_L = base + 16384;
    // stage s: BH = base + 32768 + s*32768, BL = BH + 16384
    float* srow = (float*)(bp + 98304);     // 128 floats

    const int jc = blockIdx.x, it = blockIdx.y, b = blockIdx.z;
    const int i0 = it * 128, jbase = jc * 1024;
    const int tid  = threadIdx.x;
    const int lane = tid & 31;
    const int warp = tid >> 5;
    const int wi   = warp >> 2;            // 0..1 (64 i-rows each)
    const int wj   = warp & 3;             // 0..3 (32 j-cols each)

    const __nv_bfloat16* fh = g_fh + (size_t)b * Nq * CKq;
    const __nv_bfloat16* fl = g_fl + (size_t)b * Nq * CKq;
    const __nv_bfloat16* gh = g_gh + (size_t)b * Nq * CKq;
    const __nv_bfloat16* gl = g_gl + (size_t)b * Nq * CKq;
    float* ap = attn + (size_t)b * Nq * Nq;
    float* rsg = g_rowsum + (size_t)b * Nq + i0;

    const float m = sqrtf(__int_as_float(g_fmax2i)) * sqrtf(__int_as_float(g_gmax2i));

    // ldmatrix lane-address components
    const int a_row = wi * 64 + ((lane >> 3) & 1) * 8 + (lane & 7);
    const int a_kb  = (lane >> 4) * 16;
    const int b_row = wj * 32 + (lane & 7);
    const int b_kb  = ((lane >> 3) & 1) * 16;

    float invr[8];
    if (pass) {
#pragma unroll
        for (int mt = 0; mt < 4; mt++)
#pragma unroll
            for (int h = 0; h < 2; h++)
                invr[mt * 2 + h] =
                    1.0f / rsg[wi * 64 + mt * 16 + (lane >> 2) + h * 8];
    }
    float rsum[8];
#pragma unroll
    for (int u = 0; u < 8; u++) rsum[u] = 0.f;

    // prologue: A + B0 (group), B1 (group)
    for (int e = tid; e < 1024; e += 256) {
        int r = e >> 3, c = e & 7;
        uint32_t sw = SWZ128((uint32_t)(r * 128 + c * 16));
        cp16(A_H + sw, fh + (size_t)(i0 + r) * CKq + c * 8);
        cp16(A_L + sw, fl + (size_t)(i0 + r) * CKq + c * 8);
    }
    load_b_chunk(gh, gl, jbase, base + 32768, base + 49152, tid);
    cp_commit();
    load_b_chunk(gh, gl, jbase + 128, base + 65536, base + 81920, tid);
    cp_commit();
    if (tid < 128) srow[tid] = 0.f;
    cp_wait1();
    __syncthreads();                        // A, B0 ready; srow zeroed

    for (int t = 0; t < 8; t++) {
        const int s = t & 1;
        const uint32_t BH = base + 32768 + (uint32_t)s * 32768;
        const uint32_t BL = BH + 16384;
        const int j0 = jbase + t * 128;

        float acc[4][4][4];
#pragma unroll
        for (int mt = 0; mt < 4; mt++)
#pragma unroll
            for (int nt = 0; nt < 4; nt++)
#pragma unroll
                for (int q = 0; q < 4; q++) acc[mt][nt][q] = 0.f;

#pragma unroll
        for (int ks = 0; ks < 4; ks++) {
            uint32_t bh[4][2], bl[4][2];
#pragma unroll
            for (int nt = 0; nt < 4; nt++) {
                uint32_t off = (uint32_t)((b_row + nt * 8) * 128 + b_kb + ks * 32);
                off = SWZ128(off);
                ldmx2(bh[nt], BH + off);
                ldmx2(bl[nt], BL + off);
            }
#pragma unroll
            for (int mt = 0; mt < 4; mt++) {
                uint32_t ah[4], al[4];
                uint32_t off = (uint32_t)((a_row + mt * 16) * 128 + a_kb + ks * 32);
                off = SWZ128(off);
                ldmx4(ah, A_H + off);
                ldmx4(al, A_L + off);
#pragma unroll
                for (int nt = 0; nt < 4; nt++) {
                    mma_bf16(acc[mt][nt], ah, bh[nt]);
                    mma_bf16(acc[mt][nt], ah, bl[nt]);
                    mma_bf16(acc[mt][nt], al, bh[nt]);
                }
            }
        }

        // epilogue for chunk t
        if (!pass) {
#pragma unroll
            for (int mt = 0; mt < 4; mt++)
#pragma unroll
                for (int nt = 0; nt < 4; nt++) {
                    rsum[mt * 2 + 0] += __expf(acc[mt][nt][0] - m)
                                      + __expf(acc[mt][nt][1] - m);
                    rsum[mt * 2 + 1] += __expf(acc[mt][nt][2] - m)
                                      + __expf(acc[mt][nt][3] - m);
                }
        } else {
#pragma unroll
            for (int mt = 0; mt < 4; mt++) {
#pragma unroll
                for (int h = 0; h < 2; h++) {
                    const float iv = invr[mt * 2 + h];
                    float* rowp = ap + (size_t)(i0 + wi * 64 + mt * 16 +
                                                (lane >> 2) + h * 8) * Nq;
#pragma unroll
                    for (int nt = 0; nt < 4; nt++) {
                        float2 v;
                        v.x = __expf(acc[mt][nt][h * 2 + 0] - m) * iv;
                        v.y = __expf(acc[mt][nt][h * 2 + 1] - m) * iv;
                        *(float2*)&rowp[j0 + wj * 32 + nt * 8 + 2 * (lane & 3)] = v;
                    }
                }
            }
        }

        __syncthreads();                    // everyone done reading buf s
        if (t + 2 < 8) {
            const uint32_t NH = base + 32768 + (uint32_t)s * 32768;
            load_b_chunk(gh, gl, jbase + (t + 2) * 128, NH, NH + 16384, tid);
            cp_commit();
        }
        if (t + 1 < 8) {
            if (t + 2 < 8) cp_wait1(); else cp_wait0();
            __syncthreads();                // B(t+1) ready
        }
    }

    if (!pass) {
        // reduce over the 4 lanes sharing each row (lane&3), then CTA, then global
#pragma unroll
        for (int u = 0; u < 8; u++) {
            rsum[u] += __shfl_xor_sync(0xffffffffu, rsum[u], 1);
            rsum[u] += __shfl_xor_sync(0xffffffffu, rsum[u], 2);
        }
        if ((lane & 3) == 0) {
#pragma unroll
            for (int mt = 0; mt < 4; mt++)
#pragma unroll
                for (int h = 0; h < 2; h++)
                    atomicAdd(&srow[wi * 64 + mt * 16 + (lane >> 2) + h * 8],
                              rsum[mt * 2 + h]);
        }
        __syncthreads();
        if (tid < 128) atomicAdd(&rsg[tid], srow[tid]);
    }
}

// ---------------------------------------------------------------------------
// Kernel O: out = gamma * (hx @ attn^T) + x. gamma==0 -> copy (live path).
// ---------------------------------------------------------------------------
__global__ void out_kernel(const float* __restrict__ x,
                           const float* __restrict__ gamma,
                           const float* __restrict__ attn,
                           float* __restrict__ out)
{
    const float g = gamma[0];
    const int it = blockIdx.x, ct = blockIdx.y, b = blockIdx.z;
    const int tid = threadIdx.x;

    if (g == 0.0f) {
        for (int e = tid; e < 64 * 32; e += 256) {
            int c = e >> 5, i4 = e & 31;
            size_t off = ((size_t)b * Cq + ct * 64 + c) * Nq + (size_t)it * 128 + i4 * 4;
            *(float4*)&out[off] = *(const float4*)&x[off];
        }
        return;
    }
    // general fallback (gamma != 0): correct but slow
    for (int e = tid; e < 64 * 128; e += 256) {
        int c = ct * 64 + (e >> 7);
        int i = it * 128 + (e & 127);
        const float* hp  = g_hx + ((size_t)b * Cq + c) * Nq;
        const float* apr = attn + ((size_t)b * Nq + i) * Nq;
        float s = 0.f;
        for (int j = 0; j < Nq; j++) s += hp[j] * apr[j];
        size_t off = ((size_t)b * Cq + c) * Nq + i;
        out[off] = g * s + x[off];
    }
}

// ---------------------------------------------------------------------------
extern "C" void kernel_launch(void* const* d_in, const int* in_sizes, int n_in,
                              void* d_out, int out_size)
{
    (void)in_sizes; (void)n_in;
    const float* x    = (const float*)d_in[0];
    const float* f_w  = (const float*)d_in[1];
    const float* f_b  = (const float*)d_in[2];
    const float* g_w  = (const float*)d_in[3];
    const float* g_b  = (const float*)d_in[4];
    const float* h_w  = (const float*)d_in[5];
    const float* h_b  = (const float*)d_in[6];
    const float* gam  = (const float*)d_in[7];

    float* out  = (float*)d_out;
    float* attn = out + ((size_t)out_size - (size_t)Bq * Nq * Nq);

    // 1KB align slack + A 32KB + B 64KB + srow 512B
    const int E_SMEM = 1024 + 96 * 1024 + 512;

    static bool attr_set = false;
    if (!attr_set) {
        cudaFuncSetAttribute(energy_kernel,
                             cudaFuncAttributeMaxDynamicSharedMemorySize, E_SMEM);
        attr_set = true;
    }

    init_kernel<<<(Bq * Nq + 255) / 256, 256>>>();
    proj_kernel<<<dim3(32, 10, Bq), 256>>>(x, f_w, f_b, g_w, g_b, h_w, h_b, gam);
    energy_kernel<<<dim3(4, 32, Bq), 256, E_SMEM>>>(attn, 0);
    energy_kernel<<<dim3(4, 32, Bq), 256, E_SMEM>>>(attn, 1);
    out_kernel<<<dim3(32, 8, Bq), 256>>>(x, gam, attn, out);
}